// round 1
// baseline (speedup 1.0000x reference)
#include <cuda_runtime.h>

// Round-to-nearest-even magic constant (1.5 * 2^23), valid for |y| < 2^22.
#define RMAGIC 12582912.0f
#define NLEV_M1 255.0f

// -------------------------------------------------------------------------
// Per-element math, with per-group LUT entry L = {1/d, d, -zp, 255-zp}.
// out = clip(round(x/d), -zp, 255-zp) * d
// x/d computed as x*(1/d) + one FMA Newton correction -> ~correctly rounded.
// -------------------------------------------------------------------------
template <int G>
__device__ __forceinline__ float quant1(float xv, const float* __restrict__ m,
                                        const float4* __restrict__ lut)
{
    float xa = fabsf(xv);
    int c = 0;
#pragma unroll
    for (int k = 0; k < G; k++) c += (xa >= m[k]) ? 1 : 0;
    // c in [0, G]; lut[G] duplicates lut[G-1] so no clamp needed.
    float4 L = lut[c];
    float y = xv * L.x;                     // x * (1/d)
    float r = __fmaf_rn(y, -L.y, xv);       // residual x - y*d
    y = __fmaf_rn(r, L.x, y);               // refined quotient
    float t = __fadd_rn(y, RMAGIC);         // round-to-nearest-even
    t = __fadd_rn(t, -RMAGIC);
    t = fminf(fmaxf(t, L.z), L.w);          // clip(round, -zp, 255-zp)
    return t * L.y;                         // * d
}

template <int G>
__device__ __forceinline__ float4 quant4(float4 v, const float* __restrict__ m,
                                         const float4* __restrict__ lut)
{
    float4 o;
    o.x = quant1<G>(v.x, m, lut);
    o.y = quant1<G>(v.y, m, lut);
    o.z = quant1<G>(v.z, m, lut);
    o.w = quant1<G>(v.w, m, lut);
    return o;
}

// -------------------------------------------------------------------------
// Vectorized main kernel (G known at compile time -> medians in registers).
// -------------------------------------------------------------------------
template <int G>
__global__ void __launch_bounds__(256, 4) quant_vec_kernel(
    const float4* __restrict__ x,
    const float* __restrict__ med,
    const float* __restrict__ del,
    const float* __restrict__ zp,
    float4* __restrict__ out,
    int n4)
{
    __shared__ float4 lut[G + 2];
    if (threadIdx.x < G + 1) {
        int g = (threadIdx.x < G) ? (int)threadIdx.x : (G - 1);
        float d = del[g];
        float z = zp[g];
        lut[threadIdx.x] = make_float4(__frcp_rn(d), d, -z, NLEV_M1 - z);
    }
    __syncthreads();

    float m[G];
#pragma unroll
    for (int k = 0; k < G; k++) m[k] = __ldg(med + k);

    const int stride = gridDim.x * blockDim.x;
    const int i0 = blockIdx.x * blockDim.x + threadIdx.x;
    const int per = stride * 4;
    const int nmain = (n4 / per) * per;

    // Main loop: 4 independent LDG.128 batched up front for MLP.
    for (int i = i0; i < nmain; i += per) {
        float4 v0 = __ldg(x + i);
        float4 v1 = __ldg(x + i + stride);
        float4 v2 = __ldg(x + i + 2 * stride);
        float4 v3 = __ldg(x + i + 3 * stride);
        out[i]              = quant4<G>(v0, m, lut);
        out[i + stride]     = quant4<G>(v1, m, lut);
        out[i + 2 * stride] = quant4<G>(v2, m, lut);
        out[i + 3 * stride] = quant4<G>(v3, m, lut);
    }
    // Remainder float4s.
    for (int i = nmain + i0; i < n4; i += stride) {
        out[i] = quant4<G>(__ldg(x + i), m, lut);
    }
}

// -------------------------------------------------------------------------
// Generic scalar fallback (runtime G, also used for n % 4 tail).
// Handles G up to 128.
// -------------------------------------------------------------------------
__global__ void quant_scalar_kernel(
    const float* __restrict__ x,
    const float* __restrict__ med,
    const float* __restrict__ del,
    const float* __restrict__ zp,
    float* __restrict__ out,
    int n, int G, int start)
{
    __shared__ float smed[128];
    __shared__ float4 slut[129];
    for (int t = threadIdx.x; t < G; t += blockDim.x) smed[t] = med[t];
    for (int t = threadIdx.x; t < G + 1; t += blockDim.x) {
        int g = (t < G) ? t : (G - 1);
        float d = del[g];
        float z = zp[g];
        slut[t] = make_float4(__frcp_rn(d), d, -z, NLEV_M1 - z);
    }
    __syncthreads();

    const int stride = gridDim.x * blockDim.x;
    for (int i = start + blockIdx.x * blockDim.x + threadIdx.x; i < n; i += stride) {
        float xv = x[i];
        float xa = fabsf(xv);
        int c = 0;
        for (int k = 0; k < G; k++) c += (xa >= smed[k]) ? 1 : 0;
        float4 L = slut[c];
        float y = xv * L.x;
        float r = __fmaf_rn(y, -L.y, xv);
        y = __fmaf_rn(r, L.x, y);
        float t = __fadd_rn(y, RMAGIC);
        t = __fadd_rn(t, -RMAGIC);
        t = fminf(fmaxf(t, L.z), L.w);
        out[i] = t * L.y;
    }
}

// -------------------------------------------------------------------------
// Launch
// -------------------------------------------------------------------------
extern "C" void kernel_launch(void* const* d_in, const int* in_sizes, int n_in,
                              void* d_out, int out_size)
{
    const float* x   = (const float*)d_in[0];
    const float* med = (const float*)d_in[1];
    const float* del = (const float*)d_in[2];
    const float* zp  = (const float*)d_in[3];
    float* out = (float*)d_out;

    const int n = in_sizes[0];
    const int G = in_sizes[1];

    if (G == 10) {
        const int n4 = n / 4;
        if (n4 > 0) {
            int blocks = 4096;
            int maxb = (n4 + 255) / 256;
            if (blocks > maxb) blocks = maxb;
            quant_vec_kernel<10><<<blocks, 256>>>(
                (const float4*)x, med, del, zp, (float4*)out, n4);
        }
        const int rem_start = (n / 4) * 4;
        if (rem_start < n) {
            quant_scalar_kernel<<<1, 256>>>(x, med, del, zp, out, n, G, rem_start);
        }
    } else {
        int blocks = (n + 255) / 256;
        if (blocks > 8192) blocks = 8192;
        if (blocks < 1) blocks = 1;
        quant_scalar_kernel<<<blocks, 256>>>(x, med, del, zp, out, n, G, 0);
    }
}